// round 15
// baseline (speedup 1.0000x reference)
#include <cuda_runtime.h>
#include <cuda_bf16.h>
#include <math.h>

// Problem constants: B=2, L=512 (both sides), Dh=1024, P=64, C = 4P+1 = 257
#define NB    2
#define LSEQ  512
#define DH    1024
#define PP    64
#define NCH   257
#define PLANE (LSEQ*LSEQ)      // 262144 floats per channel plane
#define PLANE4 (PLANE/4)
#define NROWS (NB*LSEQ)        // 1024 rows per side
#define NKC   32               // K chunks in projection (32 wide each)
#define HPITCH 36              // h_s row pitch in floats (144B = 9 float4, aligned)

// Scratch (device globals; no allocation allowed)
__device__ float g_part[NKC * 2 * NROWS * PP]; // [kc][side][row][p]  (16MB)
__device__ float g_za [NROWS*PP];              // side a: [b*512+i][p]
__device__ float g_zbT[NB*PP*LSEQ];            // side b: [b][p][j]
__device__ float g_na [NROWS];
__device__ float g_nb [NROWS];

// Host-side fork/join plumbing (created once at load; host objects only).
struct HxStreams {
    cudaStream_t s2;
    cudaEvent_t  e1, e2;
    HxStreams() {
        cudaStreamCreateWithFlags(&s2, cudaStreamNonBlocking);
        cudaEventCreateWithFlags(&e1, cudaEventDisableTiming);
        cudaEventCreateWithFlags(&e2, cudaEventDisableTiming);
    }
};
static HxStreams hx;

__device__ __forceinline__ float gelu_exact(float x) {
    return 0.5f * x * (1.0f + erff(x * 0.7071067811865476f));
}

// ---------------------------------------------------------------------------
// Kernel A1: partial projection GEMM over a 32-wide K chunk for ONE batch
// half (512 rows). [R14-best inner structure: 4x4 register tile, 128-thread
// blocks covering 32 rows x 64 p]. grid (16, 2, 32) = 1024 blocks per half.
// ---------------------------------------------------------------------------
__global__ __launch_bounds__(128) void proj_partial(
    const float* __restrict__ h_a, const float* __restrict__ h_b,
    const float* __restrict__ Wa,  const float* __restrict__ Wb,
    int rowOff)
{
    const int side = blockIdx.y;
    const int kc   = blockIdx.z;                 // 0..31, K chunk of 32
    const float* __restrict__ H  = side ? h_b : h_a;
    const float* __restrict__ Wp = side ? Wb  : Wa;

    const int tid = threadIdx.x;                 // 0..127
    const int tx = tid & 15;                     // p-quad 0..15
    const int ty = tid >> 4;                     // row-quad 0..7
    const int rowBase = rowOff + blockIdx.x * 32;

    __shared__ float  h_s[32 * HPITCH];          // [k][row]  (~4.6KB)
    __shared__ float4 w_s[32 * 16];              // [k][p4]    (8KB)

    // Load h chunk (32 rows x 8 float4 along k) transposed into h_s.
    {
        const float4* __restrict__ H4 = (const float4*)H;   // [row][256]
        #pragma unroll
        for (int it = 0; it < 2; ++it) {
            int idx = tid + it * 128;            // 0..255
            int r   = idx >> 3;                  // row in tile 0..31
            int c4  = idx & 7;                   // float4 index along k (0..7)
            float4 v = H4[(size_t)(rowBase + r) * 256 + kc * 8 + c4];
            h_s[(4*c4 + 0) * HPITCH + r] = v.x;
            h_s[(4*c4 + 1) * HPITCH + r] = v.y;
            h_s[(4*c4 + 2) * HPITCH + r] = v.z;
            h_s[(4*c4 + 3) * HPITCH + r] = v.w;
        }
    }
    // Load W chunk (32 k x 16 float4), coalesced, layout [k][p4].
    {
        const float4* __restrict__ W4 = (const float4*)Wp;  // [1024][16]
        #pragma unroll
        for (int it = 0; it < 4; ++it) {
            int idx = tid + it * 128;            // 0..511
            int k   = idx >> 4;
            int p4  = idx & 15;
            w_s[idx] = W4[(size_t)(kc * 32 + k) * 16 + p4];
        }
    }
    __syncthreads();

    float4 acc0 = make_float4(0.f,0.f,0.f,0.f);
    float4 acc1 = make_float4(0.f,0.f,0.f,0.f);
    float4 acc2 = make_float4(0.f,0.f,0.f,0.f);
    float4 acc3 = make_float4(0.f,0.f,0.f,0.f);

    #pragma unroll 8
    for (int k = 0; k < 32; ++k) {
        float4 h4 = *(const float4*)&h_s[k * HPITCH + ty * 4];  // 4 rows
        float4 w4 = w_s[k * 16 + tx];                           // 4 p
        acc0.x += h4.x*w4.x; acc0.y += h4.x*w4.y; acc0.z += h4.x*w4.z; acc0.w += h4.x*w4.w;
        acc1.x += h4.y*w4.x; acc1.y += h4.y*w4.y; acc1.z += h4.y*w4.z; acc1.w += h4.y*w4.w;
        acc2.x += h4.z*w4.x; acc2.y += h4.z*w4.y; acc2.z += h4.z*w4.z; acc2.w += h4.z*w4.w;
        acc3.x += h4.w*w4.x; acc3.y += h4.w*w4.y; acc3.z += h4.w*w4.z; acc3.w += h4.w*w4.w;
    }

    float4* P4 = ((float4*)g_part) + (((size_t)kc * 2 + side) * NROWS) * 16;
    const int r0 = rowBase + ty * 4;
    P4[(size_t)(r0 + 0) * 16 + tx] = acc0;
    P4[(size_t)(r0 + 1) * 16 + tx] = acc1;
    P4[(size_t)(r0 + 2) * 16 + tx] = acc2;
    P4[(size_t)(r0 + 3) * 16 + tx] = acc3;
}

// ---------------------------------------------------------------------------
// Kernel A2: reduce 32 partials for ONE batch half, bias + exact GELU,
// per-row norm, layout writes. [R14 512-thread version: kc-sum split over 4
// thread-groups + smem cross-group reduction]. grid (64, 2).
// ---------------------------------------------------------------------------
__global__ __launch_bounds__(512) void reduce_gelu(
    const float* __restrict__ ba, const float* __restrict__ bb, int rowOff)
{
    const int side = blockIdx.y;
    const float* __restrict__ bp = side ? bb : ba;
    const int tid = threadIdx.x;            // 0..511
    const int tx = tid & 15;                // p-quad
    const int ty = (tid >> 4) & 7;          // row in 8-row tile
    const int kg = tid >> 7;                // kc group 0..3
    const int row = rowOff + blockIdx.x * 8 + ty;

    const float4* P4 = (const float4*)g_part;
    float4 a = make_float4(0.f, 0.f, 0.f, 0.f);
    #pragma unroll
    for (int c = kg * 8; c < kg * 8 + 8; ++c) {
        float4 v = P4[(((size_t)c * 2 + side) * NROWS + row) * 16 + tx];
        a.x += v.x; a.y += v.y; a.z += v.z; a.w += v.w;
    }

    __shared__ float4 red_s[4][8][16];      // 8KB
    if (kg > 0) red_s[kg][ty][tx] = a;
    __syncthreads();
    if (kg != 0) return;

    {
        float4 v1 = red_s[1][ty][tx];
        float4 v2 = red_s[2][ty][tx];
        float4 v3 = red_s[3][ty][tx];
        a.x += v1.x + v2.x + v3.x;
        a.y += v1.y + v2.y + v3.y;
        a.z += v1.z + v2.z + v3.z;
        a.w += v1.w + v2.w + v3.w;
    }
    const float4 bias4 = ((const float4*)bp)[tx];

    float4 z;
    z.x = gelu_exact(a.x + bias4.x);
    z.y = gelu_exact(a.y + bias4.y);
    z.z = gelu_exact(a.z + bias4.z);
    z.w = gelu_exact(a.w + bias4.w);

    float ss = z.x*z.x + z.y*z.y + z.z*z.z + z.w*z.w;
    ss += __shfl_xor_sync(0xFFFFFFFFu, ss, 1, 16);
    ss += __shfl_xor_sync(0xFFFFFFFFu, ss, 2, 16);
    ss += __shfl_xor_sync(0xFFFFFFFFu, ss, 4, 16);
    ss += __shfl_xor_sync(0xFFFFFFFFu, ss, 8, 16);

    if (side == 0) {
        ((float4*)g_za)[(size_t)row * 16 + tx] = z;
        if (tx == 0) g_na[row] = sqrtf(ss + 1e-8f);
    } else {
        const int b = row >> 9;
        const int j = row & 511;
        const int p0 = tx * 4;
        float* dst = g_zbT + ((size_t)(b * PP + p0)) * LSEQ + j;
        dst[0*LSEQ] = z.x;
        dst[1*LSEQ] = z.y;
        dst[2*LSEQ] = z.z;
        dst[3*LSEQ] = z.w;
        if (tx == 0) g_nb[row] = sqrtf(ss + 1e-8f);
    }
}

// ---------------------------------------------------------------------------
// Kernel B: one batch's [257, LA, LB] output — R5 EXACT structure (best
// measured, __stcs), batch passed as an argument. grid (512, 1), block 128.
// ---------------------------------------------------------------------------
__global__ __launch_bounds__(128) void interact_kernel(float* __restrict__ out, int b)
{
    const int i = blockIdx.x;       // 0..511
    const int t = threadIdx.x;      // 0..127, covers j = 4t .. 4t+3

    __shared__ float za_s[PP];
    __shared__ float na_s;
    if (t < PP) za_s[t] = g_za[((size_t)(b * LSEQ + i)) * PP + t];
    if (t == 0) na_s = g_na[b * LSEQ + i];
    __syncthreads();

    const float4 nb4 = *(const float4*)&g_nb[b * LSEQ + 4 * t];

    float4* O = ((float4*)out) + (size_t)b * NCH * PLANE4 + (size_t)i * (LSEQ/4) + t;
    const float4* ZBT = ((const float4*)(g_zbT + (size_t)b * PP * LSEQ)) + t;

    float4 dot = make_float4(0.f, 0.f, 0.f, 0.f);

    #pragma unroll 4
    for (int p = 0; p < PP; ++p) {
        float4 zb = __ldg(ZBT + p * (LSEQ/4));
        float  za = za_s[p];
        float4* o = O + (size_t)p * PLANE4;

        __stcs(o,                          make_float4(za, za, za, za));
        __stcs(o + (size_t) 64 * PLANE4,   zb);
        __stcs(o + (size_t)128 * PLANE4,
               make_float4(fabsf(za - zb.x), fabsf(za - zb.y),
                           fabsf(za - zb.z), fabsf(za - zb.w)));
        __stcs(o + (size_t)192 * PLANE4,
               make_float4(za * zb.x, za * zb.y, za * zb.z, za * zb.w));

        dot.x += za * zb.x; dot.y += za * zb.y;
        dot.z += za * zb.z; dot.w += za * zb.w;
    }

    const float inv_na = 1.0f / na_s;
    float4 sim = make_float4(dot.x * inv_na / nb4.x,
                             dot.y * inv_na / nb4.y,
                             dot.z * inv_na / nb4.z,
                             dot.w * inv_na / nb4.w);
    __stcs(O + (size_t)256 * PLANE4, sim);
}

extern "C" void kernel_launch(void* const* d_in, const int* in_sizes, int n_in,
                              void* d_out, int out_size)
{
    const float* h_a = (const float*)d_in[0];
    const float* h_b = (const float*)d_in[1];
    const float* Wa  = (const float*)d_in[2];
    const float* ba  = (const float*)d_in[3];
    const float* Wb  = (const float*)d_in[4];
    const float* bb  = (const float*)d_in[5];
    float* out = (float*)d_out;

    // Batch 0 pipeline on the main stream.
    proj_partial<<<dim3(16, 2, NKC), 128>>>(h_a, h_b, Wa, Wb, 0);
    reduce_gelu <<<dim3(64, 2),      512>>>(ba, bb, 0);

    // Fork: batch-1 projection runs concurrently with interact(b0)'s
    // DRAM-bound sweep (interact uses <10% of compute issue).
    cudaEventRecord(hx.e1, 0);
    cudaStreamWaitEvent(hx.s2, hx.e1, 0);

    interact_kernel<<<dim3(LSEQ, 1), 128>>>(out, 0);

    proj_partial<<<dim3(16, 2, NKC), 128, 0, hx.s2>>>(h_a, h_b, Wa, Wb, LSEQ);
    reduce_gelu <<<dim3(64, 2),      512, 0, hx.s2>>>(ba, bb, LSEQ);
    cudaEventRecord(hx.e2, hx.s2);

    // Join: interact(b1) needs batch-1 projections.
    cudaStreamWaitEvent((cudaStream_t)0, hx.e2, 0);
    interact_kernel<<<dim3(LSEQ, 1), 128>>>(out, 1);
}

// round 16
// speedup vs baseline: 1.4945x; 1.4945x over previous
#include <cuda_runtime.h>
#include <cuda_bf16.h>
#include <math.h>

// Problem constants: B=2, L=512 (both sides), Dh=1024, P=64, C = 4P+1 = 257
#define NB    2
#define LSEQ  512
#define DH    1024
#define PP    64
#define NCH   257
#define PLANE (LSEQ*LSEQ)      // 262144 floats per channel plane
#define PLANE4 (PLANE/4)
#define NROWS (NB*LSEQ)        // 1024 rows per side
#define NKC   32               // K chunks in projection (32 wide each)
#define HPITCH 36              // h_s row pitch in floats (144B = 9 float4, aligned)

// Scratch (device globals; no allocation allowed)
__device__ float g_part[NKC * 2 * NROWS * PP]; // [kc][side][row][p]  (16MB)
__device__ float g_za [NROWS*PP];              // side a: [b*512+i][p]
__device__ float g_zbT[NB*PP*LSEQ];            // side b: [b][p][j]
__device__ float g_na [NROWS];
__device__ float g_nb [NROWS];

__device__ __forceinline__ float gelu_exact(float x) {
    return 0.5f * x * (1.0f + erff(x * 0.7071067811865476f));
}

// ---------------------------------------------------------------------------
// Kernel A1: partial projection GEMM over a 32-wide K chunk. [measured-best
// proj config: 13.4us]. 4 rows x 4 p register tile, 128-thread blocks
// covering 32 rows x 64 p. grid (32, 2, 32) = 2048 blocks.
// ---------------------------------------------------------------------------
__global__ __launch_bounds__(128) void proj_partial(
    const float* __restrict__ h_a, const float* __restrict__ h_b,
    const float* __restrict__ Wa,  const float* __restrict__ Wb)
{
    const int side = blockIdx.y;
    const int kc   = blockIdx.z;                 // 0..31, K chunk of 32
    const float* __restrict__ H  = side ? h_b : h_a;
    const float* __restrict__ Wp = side ? Wb  : Wa;

    const int tid = threadIdx.x;                 // 0..127
    const int tx = tid & 15;                     // p-quad 0..15
    const int ty = tid >> 4;                     // row-quad 0..7
    const int rowBase = blockIdx.x * 32;

    __shared__ float  h_s[32 * HPITCH];          // [k][row]  (~4.6KB)
    __shared__ float4 w_s[32 * 16];              // [k][p4]    (8KB)

    // Load h chunk (32 rows x 8 float4 along k) transposed into h_s.
    {
        const float4* __restrict__ H4 = (const float4*)H;   // [row][256]
        #pragma unroll
        for (int it = 0; it < 2; ++it) {
            int idx = tid + it * 128;            // 0..255
            int r   = idx >> 3;                  // row in tile 0..31
            int c4  = idx & 7;                   // float4 index along k (0..7)
            float4 v = H4[(size_t)(rowBase + r) * 256 + kc * 8 + c4];
            h_s[(4*c4 + 0) * HPITCH + r] = v.x;
            h_s[(4*c4 + 1) * HPITCH + r] = v.y;
            h_s[(4*c4 + 2) * HPITCH + r] = v.z;
            h_s[(4*c4 + 3) * HPITCH + r] = v.w;
        }
    }
    // Load W chunk (32 k x 16 float4), coalesced, layout [k][p4].
    {
        const float4* __restrict__ W4 = (const float4*)Wp;  // [1024][16]
        #pragma unroll
        for (int it = 0; it < 4; ++it) {
            int idx = tid + it * 128;            // 0..511
            int k   = idx >> 4;
            int p4  = idx & 15;
            w_s[idx] = W4[(size_t)(kc * 32 + k) * 16 + p4];
        }
    }
    __syncthreads();

    float4 acc0 = make_float4(0.f,0.f,0.f,0.f);
    float4 acc1 = make_float4(0.f,0.f,0.f,0.f);
    float4 acc2 = make_float4(0.f,0.f,0.f,0.f);
    float4 acc3 = make_float4(0.f,0.f,0.f,0.f);

    #pragma unroll 8
    for (int k = 0; k < 32; ++k) {
        float4 h4 = *(const float4*)&h_s[k * HPITCH + ty * 4];  // 4 rows
        float4 w4 = w_s[k * 16 + tx];                           // 4 p
        acc0.x += h4.x*w4.x; acc0.y += h4.x*w4.y; acc0.z += h4.x*w4.z; acc0.w += h4.x*w4.w;
        acc1.x += h4.y*w4.x; acc1.y += h4.y*w4.y; acc1.z += h4.y*w4.z; acc1.w += h4.y*w4.w;
        acc2.x += h4.z*w4.x; acc2.y += h4.z*w4.y; acc2.z += h4.z*w4.z; acc2.w += h4.z*w4.w;
        acc3.x += h4.w*w4.x; acc3.y += h4.w*w4.y; acc3.z += h4.w*w4.z; acc3.w += h4.w*w4.w;
    }

    float4* P4 = ((float4*)g_part) + (((size_t)kc * 2 + side) * NROWS) * 16;
    const int r0 = rowBase + ty * 4;
    P4[(size_t)(r0 + 0) * 16 + tx] = acc0;
    P4[(size_t)(r0 + 1) * 16 + tx] = acc1;
    P4[(size_t)(r0 + 2) * 16 + tx] = acc2;
    P4[(size_t)(r0 + 3) * 16 + tx] = acc3;
}

// ---------------------------------------------------------------------------
// Kernel A2: reduce 32 partials, bias + exact GELU, per-row norm, layouts.
// 512-thread blocks — kc-sum split across 4 thread-groups (8 loads each)
// with an smem cross-group reduction. grid (128, 2).
// ---------------------------------------------------------------------------
__global__ __launch_bounds__(512) void reduce_gelu(
    const float* __restrict__ ba, const float* __restrict__ bb)
{
    const int side = blockIdx.y;
    const float* __restrict__ bp = side ? bb : ba;
    const int tid = threadIdx.x;            // 0..511
    const int tx = tid & 15;                // p-quad
    const int ty = (tid >> 4) & 7;          // row in 8-row tile
    const int kg = tid >> 7;                // kc group 0..3
    const int row = blockIdx.x * 8 + ty;

    const float4* P4 = (const float4*)g_part;
    float4 a = make_float4(0.f, 0.f, 0.f, 0.f);
    #pragma unroll
    for (int c = kg * 8; c < kg * 8 + 8; ++c) {
        float4 v = P4[(((size_t)c * 2 + side) * NROWS + row) * 16 + tx];
        a.x += v.x; a.y += v.y; a.z += v.z; a.w += v.w;
    }

    __shared__ float4 red_s[4][8][16];      // 8KB
    if (kg > 0) red_s[kg][ty][tx] = a;
    __syncthreads();
    if (kg != 0) return;

    {
        float4 v1 = red_s[1][ty][tx];
        float4 v2 = red_s[2][ty][tx];
        float4 v3 = red_s[3][ty][tx];
        a.x += v1.x + v2.x + v3.x;
        a.y += v1.y + v2.y + v3.y;
        a.z += v1.z + v2.z + v3.z;
        a.w += v1.w + v2.w + v3.w;
    }
    const float4 bias4 = ((const float4*)bp)[tx];

    float4 z;
    z.x = gelu_exact(a.x + bias4.x);
    z.y = gelu_exact(a.y + bias4.y);
    z.z = gelu_exact(a.z + bias4.z);
    z.w = gelu_exact(a.w + bias4.w);

    float ss = z.x*z.x + z.y*z.y + z.z*z.z + z.w*z.w;
    ss += __shfl_xor_sync(0xFFFFFFFFu, ss, 1, 16);
    ss += __shfl_xor_sync(0xFFFFFFFFu, ss, 2, 16);
    ss += __shfl_xor_sync(0xFFFFFFFFu, ss, 4, 16);
    ss += __shfl_xor_sync(0xFFFFFFFFu, ss, 8, 16);

    if (side == 0) {
        ((float4*)g_za)[(size_t)row * 16 + tx] = z;
        if (tx == 0) g_na[row] = sqrtf(ss + 1e-8f);
    } else {
        const int b = row >> 9;
        const int j = row & 511;
        const int p0 = tx * 4;
        float* dst = g_zbT + ((size_t)(b * PP + p0)) * LSEQ + j;
        dst[0*LSEQ] = z.x;
        dst[1*LSEQ] = z.y;
        dst[2*LSEQ] = z.z;
        dst[3*LSEQ] = z.w;
        if (tx == 0) g_nb[row] = sqrtf(ss + 1e-8f);
    }
}

// ---------------------------------------------------------------------------
// Kernel B: full [B, 257, LA, LB] output — best measured (__stcs, R5 shape).
// One block per (i, b). 128 threads, each owns 4 consecutive j. Per channel p:
// one coalesced LDG.128 of zbT row + four STG.128 streaming stores; dot for
// the cosine channel accumulated in-register; sim plane stored at the end.
// ---------------------------------------------------------------------------
__global__ __launch_bounds__(128) void interact_kernel(float* __restrict__ out)
{
    const int i = blockIdx.x;       // 0..511
    const int b = blockIdx.y;       // 0..1
    const int t = threadIdx.x;      // 0..127, covers j = 4t .. 4t+3

    __shared__ float za_s[PP];
    __shared__ float na_s;
    if (t < PP) za_s[t] = g_za[((size_t)(b * LSEQ + i)) * PP + t];
    if (t == 0) na_s = g_na[b * LSEQ + i];
    __syncthreads();

    const float4 nb4 = *(const float4*)&g_nb[b * LSEQ + 4 * t];

    float4* O = ((float4*)out) + (size_t)b * NCH * PLANE4 + (size_t)i * (LSEQ/4) + t;
    const float4* ZBT = ((const float4*)(g_zbT + (size_t)b * PP * LSEQ)) + t;

    float4 dot = make_float4(0.f, 0.f, 0.f, 0.f);

    #pragma unroll 4
    for (int p = 0; p < PP; ++p) {
        float4 zb = __ldg(ZBT + p * (LSEQ/4));
        float  za = za_s[p];
        float4* o = O + (size_t)p * PLANE4;

        __stcs(o,                          make_float4(za, za, za, za));
        __stcs(o + (size_t) 64 * PLANE4,   zb);
        __stcs(o + (size_t)128 * PLANE4,
               make_float4(fabsf(za - zb.x), fabsf(za - zb.y),
                           fabsf(za - zb.z), fabsf(za - zb.w)));
        __stcs(o + (size_t)192 * PLANE4,
               make_float4(za * zb.x, za * zb.y, za * zb.z, za * zb.w));

        dot.x += za * zb.x; dot.y += za * zb.y;
        dot.z += za * zb.z; dot.w += za * zb.w;
    }

    const float inv_na = 1.0f / na_s;
    float4 sim = make_float4(dot.x * inv_na / nb4.x,
                             dot.y * inv_na / nb4.y,
                             dot.z * inv_na / nb4.z,
                             dot.w * inv_na / nb4.w);
    __stcs(O + (size_t)256 * PLANE4, sim);
}

extern "C" void kernel_launch(void* const* d_in, const int* in_sizes, int n_in,
                              void* d_out, int out_size)
{
    const float* h_a = (const float*)d_in[0];
    const float* h_b = (const float*)d_in[1];
    const float* Wa  = (const float*)d_in[2];
    const float* ba  = (const float*)d_in[3];
    const float* Wb  = (const float*)d_in[4];
    const float* bb  = (const float*)d_in[5];
    float* out = (float*)d_out;

    proj_partial<<<dim3(32, 2, NKC), 128>>>(h_a, h_b, Wa, Wb);
    reduce_gelu <<<dim3(128, 2),     512>>>(ba, bb);
    interact_kernel<<<dim3(LSEQ, NB), 128>>>(out);
}

// round 17
// speedup vs baseline: 1.5145x; 1.0134x over previous
#include <cuda_runtime.h>
#include <cuda_bf16.h>
#include <math.h>

// Problem constants: B=2, L=512 (both sides), Dh=1024, P=64, C = 4P+1 = 257
#define NB    2
#define LSEQ  512
#define DH    1024
#define PP    64
#define NCH   257
#define PLANE (LSEQ*LSEQ)      // 262144 floats per channel plane
#define PLANE4 (PLANE/4)
#define NROWS (NB*LSEQ)        // 1024 rows per side
#define NKC   32               // K chunks in projection (32 wide each)
#define HPITCH 36              // h_s row pitch in floats (144B = 9 float4, aligned)

// Scratch (device globals; no allocation allowed)
__device__ float g_part[NKC * 2 * NROWS * PP]; // [kc][side][row][p]  (16MB)
__device__ float g_za [NROWS*PP];              // side a: [b*512+i][p]
__device__ float g_zbT[NB*PP*LSEQ];            // side b: [b][p][j]
__device__ float g_na [NROWS];
__device__ float g_nb [NROWS];

__device__ __forceinline__ float gelu_exact(float x) {
    return 0.5f * x * (1.0f + erff(x * 0.7071067811865476f));
}

// ---------------------------------------------------------------------------
// Kernel A1: partial projection GEMM over a 32-wide K chunk. [measured-best
// proj config]. 4 rows x 4 p register tile, 128-thread blocks covering
// 32 rows x 64 p. grid (32, 2, 32) = 2048 blocks.
// ---------------------------------------------------------------------------
__global__ __launch_bounds__(128) void proj_partial(
    const float* __restrict__ h_a, const float* __restrict__ h_b,
    const float* __restrict__ Wa,  const float* __restrict__ Wb)
{
    const int side = blockIdx.y;
    const int kc   = blockIdx.z;                 // 0..31, K chunk of 32
    const float* __restrict__ H  = side ? h_b : h_a;
    const float* __restrict__ Wp = side ? Wb  : Wa;

    const int tid = threadIdx.x;                 // 0..127
    const int tx = tid & 15;                     // p-quad 0..15
    const int ty = tid >> 4;                     // row-quad 0..7
    const int rowBase = blockIdx.x * 32;

    __shared__ float  h_s[32 * HPITCH];          // [k][row]  (~4.6KB)
    __shared__ float4 w_s[32 * 16];              // [k][p4]    (8KB)

    // Load h chunk (32 rows x 8 float4 along k) transposed into h_s.
    {
        const float4* __restrict__ H4 = (const float4*)H;   // [row][256]
        #pragma unroll
        for (int it = 0; it < 2; ++it) {
            int idx = tid + it * 128;            // 0..255
            int r   = idx >> 3;                  // row in tile 0..31
            int c4  = idx & 7;                   // float4 index along k (0..7)
            float4 v = H4[(size_t)(rowBase + r) * 256 + kc * 8 + c4];
            h_s[(4*c4 + 0) * HPITCH + r] = v.x;
            h_s[(4*c4 + 1) * HPITCH + r] = v.y;
            h_s[(4*c4 + 2) * HPITCH + r] = v.z;
            h_s[(4*c4 + 3) * HPITCH + r] = v.w;
        }
    }
    // Load W chunk (32 k x 16 float4), coalesced, layout [k][p4].
    {
        const float4* __restrict__ W4 = (const float4*)Wp;  // [1024][16]
        #pragma unroll
        for (int it = 0; it < 4; ++it) {
            int idx = tid + it * 128;            // 0..511
            int k   = idx >> 4;
            int p4  = idx & 15;
            w_s[idx] = W4[(size_t)(kc * 32 + k) * 16 + p4];
        }
    }
    __syncthreads();

    float4 acc0 = make_float4(0.f,0.f,0.f,0.f);
    float4 acc1 = make_float4(0.f,0.f,0.f,0.f);
    float4 acc2 = make_float4(0.f,0.f,0.f,0.f);
    float4 acc3 = make_float4(0.f,0.f,0.f,0.f);

    #pragma unroll 8
    for (int k = 0; k < 32; ++k) {
        float4 h4 = *(const float4*)&h_s[k * HPITCH + ty * 4];  // 4 rows
        float4 w4 = w_s[k * 16 + tx];                           // 4 p
        acc0.x += h4.x*w4.x; acc0.y += h4.x*w4.y; acc0.z += h4.x*w4.z; acc0.w += h4.x*w4.w;
        acc1.x += h4.y*w4.x; acc1.y += h4.y*w4.y; acc1.z += h4.y*w4.z; acc1.w += h4.y*w4.w;
        acc2.x += h4.z*w4.x; acc2.y += h4.z*w4.y; acc2.z += h4.z*w4.z; acc2.w += h4.z*w4.w;
        acc3.x += h4.w*w4.x; acc3.y += h4.w*w4.y; acc3.z += h4.w*w4.z; acc3.w += h4.w*w4.w;
    }

    float4* P4 = ((float4*)g_part) + (((size_t)kc * 2 + side) * NROWS) * 16;
    const int r0 = rowBase + ty * 4;
    P4[(size_t)(r0 + 0) * 16 + tx] = acc0;
    P4[(size_t)(r0 + 1) * 16 + tx] = acc1;
    P4[(size_t)(r0 + 2) * 16 + tx] = acc2;
    P4[(size_t)(r0 + 3) * 16 + tx] = acc3;

#if __CUDA_ARCH__ >= 900
    cudaTriggerProgrammaticLaunchCompletion();
#endif
}

// ---------------------------------------------------------------------------
// Kernel A2: reduce 32 partials, bias + exact GELU, per-row norm, layouts.
// 512-thread blocks — kc-sum split across 4 thread-groups (8 loads each)
// with an smem cross-group reduction. grid (128, 2). Launched with PDL;
// waits for proj via grid-dependency sync before reading partials.
// ---------------------------------------------------------------------------
__global__ __launch_bounds__(512) void reduce_gelu(
    const float* __restrict__ ba, const float* __restrict__ bb)
{
    const int side = blockIdx.y;
    const float* __restrict__ bp = side ? bb : ba;
    const int tid = threadIdx.x;            // 0..511
    const int tx = tid & 15;                // p-quad
    const int ty = (tid >> 4) & 7;          // row in 8-row tile
    const int kg = tid >> 7;                // kc group 0..3
    const int row = blockIdx.x * 8 + ty;

#if __CUDA_ARCH__ >= 900
    cudaGridDependencySynchronize();
#endif

    const float4* P4 = (const float4*)g_part;
    float4 a = make_float4(0.f, 0.f, 0.f, 0.f);
    #pragma unroll
    for (int c = kg * 8; c < kg * 8 + 8; ++c) {
        float4 v = P4[(((size_t)c * 2 + side) * NROWS + row) * 16 + tx];
        a.x += v.x; a.y += v.y; a.z += v.z; a.w += v.w;
    }

    __shared__ float4 red_s[4][8][16];      // 8KB
    if (kg > 0) red_s[kg][ty][tx] = a;
    __syncthreads();
    if (kg != 0) return;

    {
        float4 v1 = red_s[1][ty][tx];
        float4 v2 = red_s[2][ty][tx];
        float4 v3 = red_s[3][ty][tx];
        a.x += v1.x + v2.x + v3.x;
        a.y += v1.y + v2.y + v3.y;
        a.z += v1.z + v2.z + v3.z;
        a.w += v1.w + v2.w + v3.w;
    }
    const float4 bias4 = ((const float4*)bp)[tx];

    float4 z;
    z.x = gelu_exact(a.x + bias4.x);
    z.y = gelu_exact(a.y + bias4.y);
    z.z = gelu_exact(a.z + bias4.z);
    z.w = gelu_exact(a.w + bias4.w);

    float ss = z.x*z.x + z.y*z.y + z.z*z.z + z.w*z.w;
    ss += __shfl_xor_sync(0xFFFFFFFFu, ss, 1, 16);
    ss += __shfl_xor_sync(0xFFFFFFFFu, ss, 2, 16);
    ss += __shfl_xor_sync(0xFFFFFFFFu, ss, 4, 16);
    ss += __shfl_xor_sync(0xFFFFFFFFu, ss, 8, 16);

    if (side == 0) {
        ((float4*)g_za)[(size_t)row * 16 + tx] = z;
        if (tx == 0) g_na[row] = sqrtf(ss + 1e-8f);
    } else {
        const int b = row >> 9;
        const int j = row & 511;
        const int p0 = tx * 4;
        float* dst = g_zbT + ((size_t)(b * PP + p0)) * LSEQ + j;
        dst[0*LSEQ] = z.x;
        dst[1*LSEQ] = z.y;
        dst[2*LSEQ] = z.z;
        dst[3*LSEQ] = z.w;
        if (tx == 0) g_nb[row] = sqrtf(ss + 1e-8f);
    }

#if __CUDA_ARCH__ >= 900
    cudaTriggerProgrammaticLaunchCompletion();
#endif
}

// ---------------------------------------------------------------------------
// Kernel B: full [B, 257, LA, LB] output — best measured (__stcs, R5 shape).
// One block per (i, b). 128 threads, each owns 4 consecutive j. Per channel p:
// one coalesced LDG.128 of zbT row + four STG.128 streaming stores; dot for
// the cosine channel accumulated in-register; sim plane stored at the end.
// Launched with PDL; waits for reduce before reading z/norms.
// ---------------------------------------------------------------------------
__global__ __launch_bounds__(128) void interact_kernel(float* __restrict__ out)
{
    const int i = blockIdx.x;       // 0..511
    const int b = blockIdx.y;       // 0..1
    const int t = threadIdx.x;      // 0..127, covers j = 4t .. 4t+3

#if __CUDA_ARCH__ >= 900
    cudaGridDependencySynchronize();
#endif

    __shared__ float za_s[PP];
    __shared__ float na_s;
    if (t < PP) za_s[t] = g_za[((size_t)(b * LSEQ + i)) * PP + t];
    if (t == 0) na_s = g_na[b * LSEQ + i];
    __syncthreads();

    const float4 nb4 = *(const float4*)&g_nb[b * LSEQ + 4 * t];

    float4* O = ((float4*)out) + (size_t)b * NCH * PLANE4 + (size_t)i * (LSEQ/4) + t;
    const float4* ZBT = ((const float4*)(g_zbT + (size_t)b * PP * LSEQ)) + t;

    float4 dot = make_float4(0.f, 0.f, 0.f, 0.f);

    #pragma unroll 4
    for (int p = 0; p < PP; ++p) {
        float4 zb = __ldg(ZBT + p * (LSEQ/4));
        float  za = za_s[p];
        float4* o = O + (size_t)p * PLANE4;

        __stcs(o,                          make_float4(za, za, za, za));
        __stcs(o + (size_t) 64 * PLANE4,   zb);
        __stcs(o + (size_t)128 * PLANE4,
               make_float4(fabsf(za - zb.x), fabsf(za - zb.y),
                           fabsf(za - zb.z), fabsf(za - zb.w)));
        __stcs(o + (size_t)192 * PLANE4,
               make_float4(za * zb.x, za * zb.y, za * zb.z, za * zb.w));

        dot.x += za * zb.x; dot.y += za * zb.y;
        dot.z += za * zb.z; dot.w += za * zb.w;
    }

    const float inv_na = 1.0f / na_s;
    float4 sim = make_float4(dot.x * inv_na / nb4.x,
                             dot.y * inv_na / nb4.y,
                             dot.z * inv_na / nb4.z,
                             dot.w * inv_na / nb4.w);
    __stcs(O + (size_t)256 * PLANE4, sim);
}

extern "C" void kernel_launch(void* const* d_in, const int* in_sizes, int n_in,
                              void* d_out, int out_size)
{
    const float* h_a = (const float*)d_in[0];
    const float* h_b = (const float*)d_in[1];
    const float* Wa  = (const float*)d_in[2];
    const float* ba  = (const float*)d_in[3];
    const float* Wb  = (const float*)d_in[4];
    const float* bb  = (const float*)d_in[5];
    float* out = (float*)d_out;

    // Kernel 1: normal launch.
    proj_partial<<<dim3(32, 2, NKC), 128>>>(h_a, h_b, Wa, Wb);

    // Kernels 2 and 3: PDL launches — may be scheduled during the previous
    // kernel's tail; they self-synchronize via cudaGridDependencySynchronize.
    cudaLaunchAttribute attr[1];
    attr[0].id = cudaLaunchAttributeProgrammaticStreamSerialization;
    attr[0].val.programmaticStreamSerializationAllowed = 1;

    {
        cudaLaunchConfig_t cfg = {};
        cfg.gridDim  = dim3(128, 2, 1);
        cfg.blockDim = dim3(512, 1, 1);
        cfg.attrs = attr;
        cfg.numAttrs = 1;
        cudaLaunchKernelEx(&cfg, reduce_gelu, ba, bb);
    }
    {
        cudaLaunchConfig_t cfg = {};
        cfg.gridDim  = dim3(LSEQ, NB, 1);
        cfg.blockDim = dim3(128, 1, 1);
        cfg.attrs = attr;
        cfg.numAttrs = 1;
        cudaLaunchKernelEx(&cfg, interact_kernel, out);
    }
}